// round 1
// baseline (speedup 1.0000x reference)
#include <cuda_runtime.h>

#define HH 384
#define WW 384
#define NPIX (HH * WW)
#define NSW 382     // swaps per row sweep (w = 383..2)
#define NROWS 382   // row sweeps (h = 383..2)

// Scratch (static __device__ globals: allocation-free)
__device__ float g_B1[NPIX];            // blurred input
__device__ int   g_A[NROWS * 2 * WW];   // per-sweep strip permutations (global src indices)

// Gaussian weights: sigma=0.4, radius=2, normalized (double-precision constants)
// exp(-0.5*(1/0.4)^2) = exp(-3.125), exp(-0.5*(2/0.4)^2) = exp(-12.5)
#define K0D 3.726653172078671e-06
#define K1D 0.04393693362340742
#define KSUM (1.0 + 2.0 * (K0D + K1D))
#define KW0 ((float)(K0D / KSUM))
#define KW1 ((float)(K1D / KSUM))
#define KW2 ((float)(1.0 / KSUM))

// ---------------------------------------------------------------------------
// K1: fused 2D gaussian blur (edge replicate) : img -> g_B1
// Identical to two 1D passes with per-axis edge padding (clamps are per-axis).
// ---------------------------------------------------------------------------
__global__ __launch_bounds__(256) void blur1_kernel(const float* __restrict__ in) {
    __shared__ float s[12][40];
    const float KW[5] = {KW0, KW1, KW2, KW1, KW0};

    int bx = blockIdx.x * 32, by = blockIdx.y * 8;
    int tx = threadIdx.x, ty = threadIdx.y;
    int tid = ty * 32 + tx;

    for (int cell = tid; cell < 12 * 36; cell += 256) {
        int i = cell / 36, j = cell - i * 36;
        int gr = min(max(by + i - 2, 0), HH - 1);
        int gc = min(max(bx + j - 2, 0), WW - 1);
        s[i][j] = in[gr * WW + gc];
    }
    __syncthreads();

    float acc = 0.0f;
#pragma unroll
    for (int i = 0; i < 5; i++) {
        float t = 0.0f;
#pragma unroll
        for (int j = 0; j < 5; j++) t += KW[j] * s[ty + i][tx + j];
        acc += KW[i] * t;
    }
    g_B1[(by + ty) * WW + (bx + tx)] = acc;
}

// ---------------------------------------------------------------------------
// K2: simulate each row sweep h into a strip permutation, one thread per h.
// Strip S covers rows {h-1, h}; S[x] = global source index of value at x.
// Register-carry: memory reads would only ever see identity values, so they
// are replaced by arithmetic. Zero loads besides the streamed offsets.
//
// Step at (h, w): partner (h+dy, w+dx), dx,dy in {-1,0}.
//   regs: a = S[h][w], b = S[h-1][w]  (current column)
//   identities: c = h*384+(w-1), d = (h-1)*384+(w-1)   (next column, untouched)
//   finalize S[h][w]=fa, S[h-1][w]=fb; carry (a,b) <- column w-1 post-swap.
// ---------------------------------------------------------------------------
__global__ __launch_bounds__(128) void sim_kernel(const int4* __restrict__ offs) {
    int u = blockIdx.x * blockDim.x + threadIdx.x;   // u = 383 - h
    if (u >= NROWS) return;
    int h = 383 - u;

    int* __restrict__ A0 = g_A + u * (2 * WW);   // row h-1
    int* __restrict__ A1 = A0 + WW;              // row h

    int a = h * WW + (WW - 1);       // S[h][383]
    int b = a - WW;                  // S[h-1][383]

    // offsets for this sweep: 382 consecutive int2 -> 191 int4 (16B aligned)
    const int4* __restrict__ op = offs + (size_t)u * (NSW / 2);

    int w = WW - 1;
    for (int ii = 0; ii < NSW / 2; ++ii) {
        int4 oo = op[ii];
#pragma unroll
        for (int half = 0; half < 2; ++half) {
            int dx = half ? oo.z : oo.x;
            int dy = half ? oo.w : oo.y;
            bool px = (dx != 0);             // dx == -1
            bool py = (dy != 0);             // dy == -1
            int c = h * WW + (w - 1);
            int d = c - WW;
            int fa = px ? (py ? d : c) : (py ? b : a);
            int fb = (!px && py) ? a : b;
            int na = (px && !py) ? a : c;
            int nb = (px && py) ? a : d;
            A1[w] = fa;
            A0[w] = fb;
            a = na;
            b = nb;
            --w;
        }
    }
    // w == 1 now: carry holds column 1; column 0 is never touched (identity).
    A1[1] = a;
    A0[1] = b;
    A1[0] = h * WW;
    A0[0] = (h - 1) * WW;
}

// ---------------------------------------------------------------------------
// Composed-permutation walk: g(x) = sigma_383(...sigma_2(x)...).
// Apply sigma_h for ascending h while the walker's row rho is in {h-1, h};
// once rho lands on h-1 it can never be touched again -> break. O(1) expected.
// ---------------------------------------------------------------------------
__device__ __forceinline__ int walk_src(int r0, int c0) {
    int rho = r0, c = c0;
    if (r0 >= 1) {
        int h = (r0 < 2) ? 2 : r0;
        while (true) {
            int lr = rho - (h - 1);   // 0 or 1
            int idx = g_A[(383 - h) * (2 * WW) + lr * WW + c];
            if (idx >= h * WW) {      // stayed on row h -> touched again by h+1
                rho = h;
                c = idx - h * WW;
                if (++h > 383) break;
            } else {                  // dropped to row h-1 -> done forever
                rho = h - 1;
                c = idx - rho * WW;
                break;
            }
        }
    }
    return rho * WW + c;
}

// ---------------------------------------------------------------------------
// K3: fused walk-gather + gaussian blur #2 + clip -> d_out
// Each block builds its (8+4)x(32+4) permuted-image tile in smem via walks
// (coords clamped = edge replicate of the permuted image), then blurs.
// ---------------------------------------------------------------------------
__global__ __launch_bounds__(256) void final_kernel(float* __restrict__ out) {
    __shared__ float s[12][40];
    const float KW[5] = {KW0, KW1, KW2, KW1, KW0};

    int bx = blockIdx.x * 32, by = blockIdx.y * 8;
    int tx = threadIdx.x, ty = threadIdx.y;
    int tid = ty * 32 + tx;

    for (int cell = tid; cell < 12 * 36; cell += 256) {
        int i = cell / 36, j = cell - i * 36;
        int gr = min(max(by + i - 2, 0), HH - 1);
        int gc = min(max(bx + j - 2, 0), WW - 1);
        int src = walk_src(gr, gc);
        s[i][j] = g_B1[src];
    }
    __syncthreads();

    float acc = 0.0f;
#pragma unroll
    for (int i = 0; i < 5; i++) {
        float t = 0.0f;
#pragma unroll
        for (int j = 0; j < 5; j++) t += KW[j] * s[ty + i][tx + j];
        acc += KW[i] * t;
    }
    acc = fminf(fmaxf(acc, 0.0f), 1.0f);
    out[(by + ty) * WW + (bx + tx)] = acc;
}

// ---------------------------------------------------------------------------
extern "C" void kernel_launch(void* const* d_in, const int* in_sizes, int n_in,
                              void* d_out, int out_size) {
    const float* img = (const float*)d_in[0];
    const int4* offs = (const int4*)d_in[1];   // (145924, 2) int32, 16B-aligned rows-of-2
    float* out = (float*)d_out;

    dim3 blk(32, 8);
    dim3 grd(WW / 32, HH / 8);

    sim_kernel<<<3, 128>>>(offs);     // independent of blur1; issue first
    blur1_kernel<<<grd, blk>>>(img);
    final_kernel<<<grd, blk>>>(out);
}

// round 2
// speedup vs baseline: 6.9883x; 6.9883x over previous
#include <cuda_runtime.h>

#define HH 384
#define WW 384
#define NPIX (HH * WW)
#define NSW 382     // swaps per row sweep (w = 383..2)
#define NROWS 382   // row sweeps (h = 383..2)

// Scratch (static __device__ globals: allocation-free)
__device__ float g_B1[NPIX];            // blurred input
__device__ int   g_A[NROWS * 2 * WW];   // per-sweep strip permutations (global src indices)

// Gaussian weights: sigma=0.4, radius=2, normalized (double-precision constants)
#define K0D 3.726653172078671e-06
#define K1D 0.04393693362340742
#define KSUM (1.0 + 2.0 * (K0D + K1D))
#define KW0 ((float)(K0D / KSUM))
#define KW1 ((float)(K1D / KSUM))
#define KW2 ((float)(1.0 / KSUM))

// ---------------------------------------------------------------------------
// K1: fused 2D gaussian blur (edge replicate) : img -> g_B1
// ---------------------------------------------------------------------------
__global__ __launch_bounds__(256) void blur1_kernel(const float* __restrict__ in) {
    __shared__ float s[12][40];
    const float KW[5] = {KW0, KW1, KW2, KW1, KW0};

    int bx = blockIdx.x * 32, by = blockIdx.y * 8;
    int tx = threadIdx.x, ty = threadIdx.y;
    int tid = ty * 32 + tx;

    for (int cell = tid; cell < 12 * 36; cell += 256) {
        int i = cell / 36, j = cell - i * 36;
        int gr = min(max(by + i - 2, 0), HH - 1);
        int gc = min(max(bx + j - 2, 0), WW - 1);
        s[i][j] = in[gr * WW + gc];
    }
    __syncthreads();

    float acc = 0.0f;
#pragma unroll
    for (int i = 0; i < 5; i++) {
        float t = 0.0f;
#pragma unroll
        for (int j = 0; j < 5; j++) t += KW[j] * s[ty + i][tx + j];
        acc += KW[i] * t;
    }
    g_B1[(by + ty) * WW + (bx + tx)] = acc;
}

// ---------------------------------------------------------------------------
// K2 (warp-parallel): one WARP per row sweep.
//
// Sequential recurrence per sweep (s = step index, w = 383 - s):
//   cond_s = (px_s && !py_s)
//   A_{s+1} = cond_s ? A_s : c_s          (c_s = h*384 + 382 - s)
//   B_{s+1} = (px_s && py_s) ? A_s : d_s  (d_s = c_s - 384)
// A is a pure reset-chain: A_s = h*384 + 382 - R, R = last step < s with
// !cond (R = -1 -> initial h*384+383). B_s depends only on A_{s-1} and the
// previous step's flags. So: per-lane local masks + warp max-scan of the
// last-reset index gives every lane its carry-in; then a 12-step
// register-local pass emits the strip. All offset loads are independent.
// ---------------------------------------------------------------------------
__global__ __launch_bounds__(128) void sim_kernel(const int2* __restrict__ offs) {
    int gw = (blockIdx.x * blockDim.x + threadIdx.x) >> 5;
    int lane = threadIdx.x & 31;
    if (gw >= NROWS) return;
    int u = gw, h = 383 - u;
    const int2* __restrict__ op = offs + (size_t)u * NSW;

    int s0 = 12 * lane;
    int cnt = min(NSW - s0, 12);          // lane 31 -> 10 steps

    // Phase 1: load 12 offset pairs -> flag bitmasks (independent loads)
    unsigned mpx = 0, mpy = 0;
#pragma unroll
    for (int j = 0; j < 12; j++) {
        int idx = s0 + j; if (idx > NSW - 1) idx = NSW - 1;  // clamp (dup, ignored)
        int2 oo = op[idx];
        mpx |= (oo.x ? 1u : 0u) << j;
        mpy |= (oo.y ? 1u : 0u) << j;
    }
    unsigned valid = (cnt >= 12) ? 0xFFFu : ((1u << cnt) - 1u);
    unsigned mrst = (~(mpx & ~mpy)) & valid;          // steps where A resets
    int lr_full = mrst ? (s0 + 31 - __clz(mrst)) : -1;
    unsigned m2 = mrst & ~(1u << (cnt - 1));          // resets excluding my last step
    int lr_excl = m2 ? (s0 + 31 - __clz(m2)) : -1;

    // Phase 2: inclusive max-scan of last-reset index, then exclusive carry
    int v = lr_full;
#pragma unroll
    for (int off = 1; off < 32; off <<= 1) {
        int t = __shfl_up_sync(0xFFFFFFFFu, v, off);
        if (lane >= off) v = max(v, t);
    }
    int R_in = __shfl_up_sync(0xFFFFFFFFu, v, 1);
    if (lane == 0) R_in = -1;

    int A = h * WW + 382 - R_in;          // A entering my first step (R=-1 -> +383)

    // Export to next lane: A at my LAST step + my last flags (packed)
    int myA_last = h * WW + 382 - max(R_in, lr_excl);
    unsigned pxl = (mpx >> (cnt - 1)) & 1u, pyl = (mpy >> (cnt - 1)) & 1u;
    int pack = (myA_last << 2) | (int)(pxl << 1) | (int)pyl;
    int prev = __shfl_up_sync(0xFFFFFFFFu, pack, 1);

    int B;
    if (lane == 0) {
        B = (h - 1) * WW + 383;           // initial B
    } else {
        int A_pl = prev >> 2;
        bool ppx = (prev >> 1) & 1, ppy = prev & 1;
        B = (ppx && ppy) ? A_pl : ((h - 1) * WW + 383 - s0);
    }

    // Phase 3: 12-step local pass, emit strip
    int* __restrict__ A0 = g_A + u * (2 * WW);   // row h-1
    int* __restrict__ A1 = A0 + WW;              // row h
#pragma unroll
    for (int j = 0; j < 12; j++) {
        if (j >= cnt) break;
        int s = s0 + j, w = 383 - s;
        int c = h * WW + (w - 1);
        int d = c - WW;
        bool pX = (mpx >> j) & 1u;
        bool pY = (mpy >> j) & 1u;
        int fa = pX ? (pY ? d : c) : (pY ? B : A);
        int fb = (!pX && pY) ? A : B;
        A1[w] = fa;
        A0[w] = fb;
        int nA = (pX && !pY) ? A : c;
        B = (pX && pY) ? A : d;
        A = nA;
    }
    if (lane == 31) {                     // tail: column 1 = final carry, col 0 identity
        A1[1] = A; A0[1] = B;
        A1[0] = h * WW; A0[0] = (h - 1) * WW;
    }
}

// ---------------------------------------------------------------------------
// Composed-permutation walk: g(x) = sigma_383(...sigma_2(x)...)
// ---------------------------------------------------------------------------
__device__ __forceinline__ int walk_src(int r0, int c0) {
    int rho = r0, c = c0;
    if (r0 >= 1) {
        int h = (r0 < 2) ? 2 : r0;
        while (true) {
            int lr = rho - (h - 1);   // 0 or 1
            int idx = g_A[(383 - h) * (2 * WW) + lr * WW + c];
            if (idx >= h * WW) {      // stayed on row h -> touched again by h+1
                rho = h;
                c = idx - h * WW;
                if (++h > 383) break;
            } else {                  // dropped to row h-1 -> done forever
                rho = h - 1;
                c = idx - rho * WW;
                break;
            }
        }
    }
    return rho * WW + c;
}

// ---------------------------------------------------------------------------
// K3: fused walk-gather + gaussian blur #2 + clip -> d_out
// ---------------------------------------------------------------------------
__global__ __launch_bounds__(256) void final_kernel(float* __restrict__ out) {
    __shared__ float s[12][40];
    const float KW[5] = {KW0, KW1, KW2, KW1, KW0};

    int bx = blockIdx.x * 32, by = blockIdx.y * 8;
    int tx = threadIdx.x, ty = threadIdx.y;
    int tid = ty * 32 + tx;

    for (int cell = tid; cell < 12 * 36; cell += 256) {
        int i = cell / 36, j = cell - i * 36;
        int gr = min(max(by + i - 2, 0), HH - 1);
        int gc = min(max(bx + j - 2, 0), WW - 1);
        int src = walk_src(gr, gc);
        s[i][j] = g_B1[src];
    }
    __syncthreads();

    float acc = 0.0f;
#pragma unroll
    for (int i = 0; i < 5; i++) {
        float t = 0.0f;
#pragma unroll
        for (int j = 0; j < 5; j++) t += KW[j] * s[ty + i][tx + j];
        acc += KW[i] * t;
    }
    acc = fminf(fmaxf(acc, 0.0f), 1.0f);
    out[(by + ty) * WW + (bx + tx)] = acc;
}

// ---------------------------------------------------------------------------
extern "C" void kernel_launch(void* const* d_in, const int* in_sizes, int n_in,
                              void* d_out, int out_size) {
    const float* img = (const float*)d_in[0];
    const int2* offs = (const int2*)d_in[1];   // (145924, 2) int32 pairs (dx, dy)
    float* out = (float*)d_out;

    dim3 blk(32, 8);
    dim3 grd(WW / 32, HH / 8);

    sim_kernel<<<(NROWS * 32 + 127) / 128, 128>>>(offs);
    blur1_kernel<<<grd, blk>>>(img);
    final_kernel<<<grd, blk>>>(out);
}